// round 5
// baseline (speedup 1.0000x reference)
#include <cuda_runtime.h>
#include <cstdint>
#include <math.h>

#define N_NODES 50000
#define E_EDGES 800000
#define F_IN    128
#define HID     96
#define L_LAYERS 4
#define FULLM 0xffffffffu

// ---------------- device scratch ----------------
__device__ __align__(16) float g_h   [N_NODES * HID];
__device__ __align__(16) float g_hn  [N_NODES * HID];
__device__ __align__(16) float g_xlxr[N_NODES * 2 * HID];   // stride 192: [0:96)=xl, [96:192)=xr
__device__ __align__(16) int   g_cnt   [N_NODES];
__device__ __align__(16) int   g_rowptr[N_NODES + 1];
__device__ __align__(16) int   g_cursor[N_NODES];
__device__ __align__(16) int2  g_edge  [E_EDGES];   // (src, ew bits), sorted by dst
__device__ int g_is64;

// ---------------- edge_index dtype sniff ----------------
__global__ void detect_kernel(const int* ei32) {
    bool is64 = true;
    #pragma unroll
    for (int i = 0; i < 8; i++) if (ei32[2 * i + 1] != 0) is64 = false;
    g_is64 = is64 ? 1 : 0;
}

__device__ __forceinline__ void load_edge(const void* ei, int e, int& s, int& d) {
    if (g_is64) {
        const long long* p = (const long long*)ei;
        s = (int)p[e]; d = (int)p[E_EDGES + e];
    } else {
        const int* p = (const int*)ei;
        s = p[e]; d = p[E_EDGES + e];
    }
}

// ---------------- CSR build ----------------
__global__ void __launch_bounds__(256) hist_kernel(const void* ei) {
    int base = (blockIdx.x * blockDim.x + threadIdx.x) * 2;
    #pragma unroll
    for (int i = 0; i < 2; i++) {
        int e = base + i;
        if (e < E_EDGES) {
            int s, d; load_edge(ei, e, s, d);
            atomicAdd(&g_cnt[d], 1);
        }
    }
}

__global__ void __launch_bounds__(1024) scan_kernel() {
    __shared__ int ps[1024];
    int t = threadIdx.x;
    const int CH = (N_NODES + 1023) / 1024;
    int base = t * CH;
    int sum = 0;
    for (int i = 0; i < CH; i++) {
        int idx = base + i;
        if (idx < N_NODES) sum += g_cnt[idx];
    }
    ps[t] = sum;
    __syncthreads();
    for (int off = 1; off < 1024; off <<= 1) {
        int v = (t >= off) ? ps[t - off] : 0;
        __syncthreads();
        ps[t] += v;
        __syncthreads();
    }
    int run = ps[t] - sum;
    for (int i = 0; i < CH; i++) {
        int idx = base + i;
        if (idx < N_NODES) {
            g_rowptr[idx] = run;
            g_cursor[idx] = run;
            run += g_cnt[idx];
        }
    }
    if (t == 0) g_rowptr[N_NODES] = E_EDGES;
}

__global__ void __launch_bounds__(256) scatter_kernel(const void* ei, const float* __restrict__ ew) {
    int base = (blockIdx.x * blockDim.x + threadIdx.x) * 2;
    #pragma unroll
    for (int i = 0; i < 2; i++) {
        int e = base + i;
        if (e < E_EDGES) {
            int s, d; load_edge(ei, e, s, d);
            int p = atomicAdd(&g_cursor[d], 1);
            g_edge[p] = make_int2(s, __float_as_int(ew[e]));
        }
    }
}

// ---------------- packed-f32x2 helpers ----------------
__device__ __forceinline__ unsigned long long lds64(unsigned addr) {
    unsigned long long v;
    asm volatile("ld.shared.b64 %0, [%1];" : "=l"(v) : "r"(addr));
    return v;
}
__device__ __forceinline__ float lds32(unsigned addr) {
    float v;
    asm volatile("ld.shared.f32 %0, [%1];" : "=f"(v) : "r"(addr));
    return v;
}
__device__ __forceinline__ void ffma2(unsigned long long& d, unsigned long long a, unsigned long long b) {
    asm volatile("fma.rn.f32x2 %0, %1, %2, %0;" : "+l"(d) : "l"(a), "l"(b));
}
__device__ __forceinline__ unsigned long long pack2(float a) {
    unsigned long long v;
    asm("mov.b64 %0, {%1,%1};" : "=l"(v) : "f"(a));
    return v;
}

// ---------------- GEMM v2: C[nrows,CW] = A[nrows,K] @ [W1|W2] + [b1|b2] ----------------
// 256 threads; thread tile 8 rows x CPT col-pairs; block tile 128 rows x CW cols.
// A scalar in smem (broadcast, packed in-register); W column-pairs via LDS.64.
template <int K, int CW, int CW1, int CPT>
__global__ void __launch_bounds__(256, 1) gemm2_kernel(
    const float* __restrict__ A,
    const float* __restrict__ W1, const float* __restrict__ W2,
    const float* __restrict__ b1, const float* __restrict__ b2,
    float* __restrict__ C, int nrows)
{
    constexpr int KCH = 32;
    constexpr int RPB = 128;
    constexpr int RPT = 8;

    __shared__ float As[RPB * KCH];   // 16 KB
    __shared__ float Ws[KCH * CW];    // 24 KB (CW=192) / 12 KB (CW=96)

    const int tid = threadIdx.x;
    const int cx  = tid & 15;     // 16 col lanes; cols: 2*cx + 32*c
    const int ry  = tid >> 4;     // 16 row groups; rows: ry + 16*j
    const int rowbase = blockIdx.x * RPB;

    unsigned aB = (unsigned)__cvta_generic_to_shared(As);
    unsigned wB = (unsigned)__cvta_generic_to_shared(Ws);

    unsigned long long acc[RPT][CPT];
    #pragma unroll
    for (int j = 0; j < RPT; j++)
        #pragma unroll
        for (int c = 0; c < CPT; c++) acc[j][c] = 0ULL;

    for (int kc = 0; kc < K; kc += KCH) {
        // A tile (128 x 32): 4 float4 per thread
        #pragma unroll
        for (int i = 0; i < 4; i++) {
            int f4  = tid + i * 256;
            int row = f4 >> 3;
            int kk  = (f4 & 7) * 4;
            float4 v = make_float4(0.f, 0.f, 0.f, 0.f);
            int grow = rowbase + row;
            if (grow < nrows) v = *(const float4*)(A + (size_t)grow * K + kc + kk);
            *(float4*)(As + row * KCH + kk) = v;
        }
        // W tile (32 x CW)
        #pragma unroll
        for (int i = 0; i < (KCH * CW) / 1024; i++) {
            int f = (tid + i * 256) * 4;
            int k = f / CW;
            int c = f % CW;
            float4 v;
            if (c < CW1) v = *(const float4*)(W1 + (size_t)(kc + k) * CW1 + c);
            else         v = *(const float4*)(W2 + (size_t)(kc + k) * (CW - CW1) + (c - CW1));
            *(float4*)(Ws + k * CW + c) = v;
        }
        __syncthreads();

        #pragma unroll 4
        for (int kk = 0; kk < KCH; kk++) {
            unsigned long long av[RPT];
            #pragma unroll
            for (int j = 0; j < RPT; j++)
                av[j] = pack2(lds32(aB + (unsigned)(((ry + 16 * j) * KCH + kk) << 2)));
            unsigned long long wv[CPT];
            #pragma unroll
            for (int c = 0; c < CPT; c++)
                wv[c] = lds64(wB + (unsigned)((kk * CW + 2 * cx + 32 * c) << 2));
            #pragma unroll
            for (int j = 0; j < RPT; j++)
                #pragma unroll
                for (int c = 0; c < CPT; c++) ffma2(acc[j][c], av[j], wv[c]);
        }
        __syncthreads();
    }

    #pragma unroll
    for (int c = 0; c < CPT; c++) {
        int col = 2 * cx + 32 * c;
        float bv0, bv1;
        if (col < CW1) { bv0 = b1[col];       bv1 = b1[col + 1]; }
        else           { bv0 = b2[col - CW1]; bv1 = b2[col - CW1 + 1]; }
        #pragma unroll
        for (int j = 0; j < RPT; j++) {
            int grow = rowbase + ry + 16 * j;
            if (grow < nrows) {
                float lo, hi;
                asm("mov.b64 {%0,%1}, %2;" : "=f"(lo), "=f"(hi) : "l"(acc[j][c]));
                *(float2*)(C + (size_t)grow * CW + col) = make_float2(lo + bv0, hi + bv1);
            }
        }
    }
}

// ---------------- warp reduce ----------------
__device__ __forceinline__ float wsum(float v) {
    #pragma unroll
    for (int o = 16; o > 0; o >>= 1) v += __shfl_xor_sync(FULLM, v, o);
    return v;
}
__device__ __forceinline__ float wmax(float v) {
    #pragma unroll
    for (int o = 16; o > 0; o >>= 1) v = fmaxf(v, __shfl_xor_sync(FULLM, v, o));
    return v;
}

// ---------------- initial LayerNorm + ReLU (h -> hn) ----------------
__global__ void __launch_bounds__(256) ln_init_kernel(
    const float* __restrict__ h,
    const float* __restrict__ g, const float* __restrict__ b,
    float* __restrict__ hn)
{
    int warp = threadIdx.x >> 5;
    int lane = threadIdx.x & 31;
    int n = blockIdx.x * 8 + warp;
    if (n >= N_NODES) return;
    size_t base = (size_t)n * HID;

    float v0 = h[base + lane], v1 = h[base + lane + 32], v2 = h[base + lane + 64];
    float mean = wsum(v0 + v1 + v2) * (1.0f / HID);
    float d0 = v0 - mean, d1 = v1 - mean, d2 = v2 - mean;
    float rstd = rsqrtf(wsum(fmaf(d0, d0, fmaf(d1, d1, d2 * d2))) * (1.0f / HID) + 1e-5f);
    hn[base + lane]      = fmaxf(fmaf(d0 * rstd, g[lane],      b[lane]),      0.f);
    hn[base + lane + 32] = fmaxf(fmaf(d1 * rstd, g[lane + 32], b[lane + 32]), 0.f);
    hn[base + lane + 64] = fmaxf(fmaf(d2 * rstd, g[lane + 64], b[lane + 64]), 0.f);
}

// ---------------- fused GAT layer ----------------
// Warp per node. Per 32-edge chunk:
//   pass A: 4 edges concurrently, 8 lanes each (3-shuffle sub-group reduce)
//   chunk-level online-softmax merge (one exp correction per chunk)
//   pass B: aggregation re-gathering the same rows (L1-hot, same launch)
__global__ void __launch_bounds__(256) gat_fused_kernel(
    const float* __restrict__ We,  const float* __restrict__ att,
    const float* __restrict__ bias,
    const float* __restrict__ lg,  const float* __restrict__ lb)
{
    __shared__ float sWe[HID], sAtt[HID], sBias[HID], sG[HID], sB[HID];
    int t = threadIdx.x;
    if (t < HID) {
        sWe[t] = We[t]; sAtt[t] = att[t]; sBias[t] = bias[t];
        sG[t] = lg[t];  sB[t]  = lb[t];
    }
    __syncthreads();

    int warp = t >> 5, lane = t & 31;
    int n = blockIdx.x * 8 + warp;
    if (n >= N_NODES) return;

    int l8  = lane & 7;
    int grp = lane >> 3;

    int r0 = g_rowptr[n], r1 = g_rowptr[n + 1];
    const float* xrp = g_xlxr + (size_t)n * 192 + 96;

    // float4 layout for pass A (lane covers dims l8*4 + c*32 + {0..3})
    float4 xr4[3], we4[3], at4[3];
    #pragma unroll
    for (int c = 0; c < 3; c++) {
        int k = c * 32 + l8 * 4;
        xr4[c] = *(const float4*)(xrp + k);
        we4[c] = *(const float4*)(sWe + k);
        at4[c] = *(const float4*)(sAtt + k);
    }

    float m = -INFINITY, ssum = 0.f;
    float a0 = 0.f, a1 = 0.f, a2 = 0.f;

    for (int c0 = r0; c0 < r1; c0 += 32) {
        int cnt = min(32, r1 - c0);
        int p = c0 + lane;
        int   si = 0;
        float wE = 0.f;
        if (lane < cnt) {
            int2 ed = g_edge[p];
            si = ed.x;
            wE = __int_as_float(ed.y);
        }

        // ---- pass A: 4 edges per iteration, 8-lane sub-group reduction
        float myal = -INFINITY;
        int iters = (cnt + 3) >> 2;
        for (int i = 0; i < iters; i++) {
            int eidx = 4 * i + grp;               // < 32 always
            int   se  = __shfl_sync(FULLM, si, eidx);
            float wEe = __shfl_sync(FULLM, wE, eidx);
            const float* xa = g_xlxr + (size_t)se * 192;

            float part = 0.f;
            #pragma unroll
            for (int c = 0; c < 3; c++) {
                float4 a = *(const float4*)(xa + c * 32 + l8 * 4);
                float4 r = xr4[c], w4 = we4[c], t4 = at4[c];
                float e0 = fmaf(wEe, w4.x, a.x + r.x); e0 = fmaxf(e0, 0.2f * e0);
                float e1 = fmaf(wEe, w4.y, a.y + r.y); e1 = fmaxf(e1, 0.2f * e1);
                float e2 = fmaf(wEe, w4.z, a.z + r.z); e2 = fmaxf(e2, 0.2f * e2);
                float e3 = fmaf(wEe, w4.w, a.w + r.w); e3 = fmaxf(e3, 0.2f * e3);
                part = fmaf(e0, t4.x, fmaf(e1, t4.y, fmaf(e2, t4.z, fmaf(e3, t4.w, part))));
            }
            part += __shfl_xor_sync(FULLM, part, 4);
            part += __shfl_xor_sync(FULLM, part, 2);
            part += __shfl_xor_sync(FULLM, part, 1);

            float bc = __shfl_sync(FULLM, part, (lane & 3) * 8);
            if ((lane >> 2) == i && lane < cnt) myal = bc;
        }

        // ---- chunk-level online softmax merge
        float cm = wmax(myal);
        float nm = fmaxf(m, cm);
        float corr = __expf(m - nm);
        ssum *= corr; a0 *= corr; a1 *= corr; a2 *= corr;
        float wexp = (lane < cnt) ? __expf(myal - nm) : 0.f;
        ssum += wsum(wexp);
        m = nm;

        // ---- pass B: aggregation (rows L1-hot from pass A)
        int jj = 0;
        for (; jj + 4 <= cnt; jj += 4) {
            float w0 = __shfl_sync(FULLM, wexp, jj + 0);
            float w1 = __shfl_sync(FULLM, wexp, jj + 1);
            float w2 = __shfl_sync(FULLM, wexp, jj + 2);
            float w3 = __shfl_sync(FULLM, wexp, jj + 3);
            const float* x0p = g_xlxr + (size_t)__shfl_sync(FULLM, si, jj + 0) * 192;
            const float* x1p = g_xlxr + (size_t)__shfl_sync(FULLM, si, jj + 1) * 192;
            const float* x2p = g_xlxr + (size_t)__shfl_sync(FULLM, si, jj + 2) * 192;
            const float* x3p = g_xlxr + (size_t)__shfl_sync(FULLM, si, jj + 3) * 192;
            float v00 = x0p[lane], v01 = x0p[lane + 32], v02 = x0p[lane + 64];
            float v10 = x1p[lane], v11 = x1p[lane + 32], v12 = x1p[lane + 64];
            float v20 = x2p[lane], v21 = x2p[lane + 32], v22 = x2p[lane + 64];
            float v30 = x3p[lane], v31 = x3p[lane + 32], v32 = x3p[lane + 64];
            a0 = fmaf(w0, v00, a0); a1 = fmaf(w0, v01, a1); a2 = fmaf(w0, v02, a2);
            a0 = fmaf(w1, v10, a0); a1 = fmaf(w1, v11, a1); a2 = fmaf(w1, v12, a2);
            a0 = fmaf(w2, v20, a0); a1 = fmaf(w2, v21, a1); a2 = fmaf(w2, v22, a2);
            a0 = fmaf(w3, v30, a0); a1 = fmaf(w3, v31, a1); a2 = fmaf(w3, v32, a2);
        }
        for (; jj < cnt; jj++) {
            float w = __shfl_sync(FULLM, wexp, jj);
            const float* xp = g_xlxr + (size_t)__shfl_sync(FULLM, si, jj) * 192;
            a0 = fmaf(w, xp[lane],      a0);
            a1 = fmaf(w, xp[lane + 32], a1);
            a2 = fmaf(w, xp[lane + 64], a2);
        }
    }

    float inv = 1.0f / (ssum + 1e-16f);
    a0 *= inv; a1 *= inv; a2 *= inv;

    // ---- residual + bias + LayerNorm + ReLU
    size_t base = (size_t)n * HID;
    float x0 = g_h[base + lane]      + a0 + sBias[lane];
    float x1 = g_h[base + lane + 32] + a1 + sBias[lane + 32];
    float x2 = g_h[base + lane + 64] + a2 + sBias[lane + 64];
    g_h[base + lane]      = x0;
    g_h[base + lane + 32] = x1;
    g_h[base + lane + 64] = x2;

    float mean = wsum(x0 + x1 + x2) * (1.0f / HID);
    float d0 = x0 - mean, d1 = x1 - mean, d2 = x2 - mean;
    float rstd = rsqrtf(wsum(fmaf(d0, d0, fmaf(d1, d1, d2 * d2))) * (1.0f / HID) + 1e-5f);
    g_hn[base + lane]      = fmaxf(fmaf(d0 * rstd, sG[lane],      sB[lane]),      0.f);
    g_hn[base + lane + 32] = fmaxf(fmaf(d1 * rstd, sG[lane + 32], sB[lane + 32]), 0.f);
    g_hn[base + lane + 64] = fmaxf(fmaf(d2 * rstd, sG[lane + 64], sB[lane + 64]), 0.f);
}

// ---------------- final FC ----------------
__global__ void __launch_bounds__(256) fc_kernel(
    const float* __restrict__ fcW, const float* __restrict__ fcb,
    float* __restrict__ out)
{
    int warp = threadIdx.x >> 5;
    int lane = threadIdx.x & 31;
    int n = blockIdx.x * 8 + warp;
    if (n >= N_NODES) return;
    size_t base = (size_t)n * HID;
    float acc = fmaf(g_hn[base + lane], fcW[lane],
                fmaf(g_hn[base + lane + 32], fcW[lane + 32],
                     g_hn[base + lane + 64] * fcW[lane + 64]));
    acc = wsum(acc);
    if (lane == 0) out[n] = acc + fcb[0];
}

// ---------------- launch ----------------
extern "C" void kernel_launch(void* const* d_in, const int* in_sizes, int n_in,
                              void* d_out, int out_size)
{
    const float* x    = (const float*)d_in[0];
    const void*  ei   = (const void*) d_in[1];
    const float* ew   = (const float*)d_in[2];
    const float* encW = (const float*)d_in[3];
    const float* encb = (const float*)d_in[4];
    const float* Wl   = (const float*)d_in[5];
    const float* bl   = (const float*)d_in[6];
    const float* Wr   = (const float*)d_in[7];
    const float* br   = (const float*)d_in[8];
    const float* We   = (const float*)d_in[9];
    const float* att  = (const float*)d_in[10];
    const float* bias = (const float*)d_in[11];
    const float* lng  = (const float*)d_in[12];
    const float* lnb  = (const float*)d_in[13];
    const float* lnfg = (const float*)d_in[14];
    const float* lnfb = (const float*)d_in[15];
    const float* fcW  = (const float*)d_in[16];
    const float* fcb  = (const float*)d_in[17];
    float*       out  = (float*)d_out;

    void *p_h, *p_hn, *p_cnt, *p_xlxr;
    cudaGetSymbolAddress(&p_h,    g_h);
    cudaGetSymbolAddress(&p_hn,   g_hn);
    cudaGetSymbolAddress(&p_cnt,  g_cnt);
    cudaGetSymbolAddress(&p_xlxr, g_xlxr);

    const int gemm_blocks  = (N_NODES + 127) / 128;     // 391
    const int node_blocks  = (N_NODES + 7) / 8;         // 6250
    const int edge2_blocks = (E_EDGES / 2 + 255) / 256; // 1563

    // CSR build (once per launch, shared by all 4 layers)
    detect_kernel<<<1, 1>>>((const int*)ei);
    cudaMemsetAsync(p_cnt, 0, N_NODES * sizeof(int));
    hist_kernel<<<edge2_blocks, 256>>>(ei);
    scan_kernel<<<1, 1024>>>();
    scatter_kernel<<<edge2_blocks, 256>>>(ei, ew);

    // encoder + first LN
    gemm2_kernel<F_IN, HID, HID, 3><<<gemm_blocks, 256>>>(
        x, encW, encW, encb, encb, (float*)p_h, N_NODES);
    ln_init_kernel<<<node_blocks, 256>>>((const float*)p_h, lng, lnb, (float*)p_hn);

    for (int i = 0; i < L_LAYERS; i++) {
        gemm2_kernel<HID, 2 * HID, HID, 6><<<gemm_blocks, 256>>>(
            (const float*)p_hn,
            Wl + (size_t)i * HID * HID, Wr + (size_t)i * HID * HID,
            bl + i * HID, br + i * HID, (float*)p_xlxr, N_NODES);

        const float* gnext = (i < L_LAYERS - 1) ? (lng + (i + 1) * HID) : lnfg;
        const float* bnext = (i < L_LAYERS - 1) ? (lnb + (i + 1) * HID) : lnfb;
        gat_fused_kernel<<<node_blocks, 256>>>(
            We + i * HID, att + i * HID, bias + i * HID, gnext, bnext);
    }

    fc_kernel<<<node_blocks, 256>>>(fcW, fcb, out);
}